// round 8
// baseline (speedup 1.0000x reference)
#include <cuda_runtime.h>
#include <cuda_fp16.h>
#include <cstdint>

#define NMAX 400000
#define EMAX 1600000
#define GMAX 4096
#define HD   128
#define CHUNK 1024

// -------- device scratch --------
__device__ int    g_counts [NMAX];
__device__ int    g_rowptr [NMAX + 1];
__device__ int    g_cursor [NMAX];
__device__ int    g_colidx [EMAX];
__device__ int    g_bsum   [512];
__device__ int    g_boff   [512];
__device__ float  g_dinv   [NMAX];
__device__ __half g_xs     [(size_t)NMAX * 80];    // x*dinv fp16, stride 80 (cols 78,79 = 0)
__device__ __half g_hh     [(size_t)NMAX * 128];   // h0*dinv after fused layer 0
__device__ __half g_h1     [(size_t)NMAX * 128];   // h1 after fused layer 1
__device__ __half g_w0t    [128 * 96];             // W0^T fp16 [n][k], k padded to 96
__device__ __half g_w1t    [128 * 128];            // W1^T fp16 [n][k]
__device__ float  g_pool   [(size_t)GMAX * HD];
__device__ float  g_ff     [(size_t)GMAX * 256];

// ---------------- degree / CSR build ----------------
__global__ void zero_counts_kernel(int* counts, int N) {
    int i = blockIdx.x * blockDim.x + threadIdx.x;
    if (i < N) counts[i] = 0;
}

__global__ void count_deg_kernel(const int* __restrict__ dst, int* counts, int E) {
    int e = blockIdx.x * blockDim.x + threadIdx.x;
    if (e < E) atomicAdd(&counts[dst[e]], 1);
}

__global__ void dinv_kernel(const int* __restrict__ counts, float* dinv, int N) {
    int i = blockIdx.x * blockDim.x + threadIdx.x;
    if (i < N) dinv[i] = rsqrtf((float)counts[i] + 1.0f);
}

__global__ void scan_chunk_sum(const int* __restrict__ counts, int* bsum, int N) {
    __shared__ int sh[256];
    int base = blockIdx.x * CHUNK;
    int s = 0;
    for (int i = threadIdx.x; i < CHUNK; i += 256) {
        int g = base + i;
        s += (g < N) ? counts[g] : 0;
    }
    sh[threadIdx.x] = s; __syncthreads();
    for (int o = 128; o > 0; o >>= 1) {
        if (threadIdx.x < o) sh[threadIdx.x] += sh[threadIdx.x + o];
        __syncthreads();
    }
    if (threadIdx.x == 0) bsum[blockIdx.x] = sh[0];
}

__global__ void scan_bsum(const int* __restrict__ bsum, int* boff, int NB) {
    __shared__ int sh[512];
    int v = (threadIdx.x < NB) ? bsum[threadIdx.x] : 0;
    sh[threadIdx.x] = v; __syncthreads();
    for (int o = 1; o < 512; o <<= 1) {
        int t = (threadIdx.x >= o) ? sh[threadIdx.x - o] : 0;
        __syncthreads();
        sh[threadIdx.x] += t;
        __syncthreads();
    }
    if (threadIdx.x < NB) boff[threadIdx.x] = sh[threadIdx.x] - v;  // exclusive
}

__global__ void scan_final(const int* __restrict__ counts, const int* __restrict__ boff,
                           int* rowptr, int* cursor, int N) {
    __shared__ int sh[CHUNK];
    int g = blockIdx.x * CHUNK + threadIdx.x;
    int v = (g < N) ? counts[g] : 0;
    sh[threadIdx.x] = v; __syncthreads();
    for (int o = 1; o < CHUNK; o <<= 1) {
        int t = (threadIdx.x >= o) ? sh[threadIdx.x - o] : 0;
        __syncthreads();
        sh[threadIdx.x] += t;
        __syncthreads();
    }
    if (g < N) {
        int excl = boff[blockIdx.x] + sh[threadIdx.x] - v;
        rowptr[g] = excl;
        cursor[g] = excl;
        if (g == N - 1) rowptr[N] = boff[blockIdx.x] + sh[threadIdx.x];
    }
}

__global__ void fill_csr_kernel(const int* __restrict__ src, const int* __restrict__ dst,
                                int* cursor, int* colidx, int E) {
    int e = blockIdx.x * blockDim.x + threadIdx.x;
    if (e < E) {
        int d = dst[e];
        int p = atomicAdd(&cursor[d], 1);
        colidx[p] = src[e];
    }
}

// ---------------- conversions ----------------
__global__ void conv_x_kernel(const float* __restrict__ x, const float* __restrict__ dinv,
                              __half2* __restrict__ xs2, int N) {
    int i = blockIdx.x * blockDim.x + threadIdx.x;   // over N*40 half2
    if (i >= N * 40) return;
    int n = i / 40;
    int c = i - n * 40;
    float dd = __ldg(&dinv[n]);
    float v0 = (2 * c     < 78) ? x[(size_t)n * 78 + 2 * c]     * dd : 0.0f;
    float v1 = (2 * c + 1 < 78) ? x[(size_t)n * 78 + 2 * c + 1] * dd : 0.0f;
    xs2[i] = __floats2half2_rn(v0, v1);
}

__global__ void conv_w0t_kernel(const float* __restrict__ W0, __half* __restrict__ W0t) {
    int i = blockIdx.x * blockDim.x + threadIdx.x;   // 128*96
    if (i >= 128 * 96) return;
    int n = i / 96;
    int k = i - n * 96;
    W0t[i] = (k < 78) ? __float2half_rn(W0[(size_t)k * 128 + n]) : __float2half_rn(0.0f);
}

__global__ void conv_w1t_kernel(const float* __restrict__ W1, __half* __restrict__ W1t) {
    int i = blockIdx.x * blockDim.x + threadIdx.x;   // 128*128
    if (i >= 128 * 128) return;
    int n = i >> 7;
    int k = i & 127;
    W1t[i] = __float2half_rn(W1[(size_t)k * 128 + n]);
}

// ---------------- fused aggregate + GEMM ----------------
// Block = 256 threads (8 warps), owns 128 nodes (rows) x 128 out cols.
// Phase 0: prefetch Wt (n-major, [128, KH] halves) into Bs smem via cp.async.
// Phase 1: each warp aggregates 16 node rows into As smem (fp16, stride KH+8).
//          row(m) = dinv[node] * ( src[node] + sum_{s in N(node)} src[s] )   (src already *dinv)
// Phase 2: mma.m16n8k16 over K; epilogue relu(acc+bias)[*rowscale] -> out fp16 [M,128].
// SRCW = src row width in half2 (40 for layer0 / 64 for layer1); KH = 96 or 128 halves.
template<int SRCW, int KH>
__global__ void __launch_bounds__(256, 2)
fused_agg_gemm(const __half2* __restrict__ src2, const int* __restrict__ rowptr,
               const int* __restrict__ colidx, const float* __restrict__ dinv,
               const __half* __restrict__ Wt, const float* __restrict__ bias,
               const float* __restrict__ rowscale, __half* __restrict__ out)
{
    constexpr int ASTR = KH + 8;   // smem row stride in halves
    extern __shared__ __half sm[];
    __half* As = sm;                       // 128 * ASTR
    __half* Bs = sm + 128 * ASTR;          // 128 * ASTR

    const int tid  = threadIdx.x;
    const int row0 = blockIdx.x * 128;
    const int lane = tid & 31;
    const int wid  = tid >> 5;

    // ---- phase 0: prefetch all of Wt into Bs ----
    constexpr int BCH = KH / 8;            // 16-byte chunks per n-row
    for (int i = tid; i < 128 * BCH; i += 256) {
        int n = i / BCH, ch = i - n * BCH;
        const __half* srcw = Wt + (size_t)n * KH + ch * 8;
        uint32_t dst = (uint32_t)__cvta_generic_to_shared(&Bs[n * ASTR + ch * 8]);
        asm volatile("cp.async.cg.shared.global [%0], [%1], 16;" :: "r"(dst), "l"(srcw));
    }
    asm volatile("cp.async.commit_group;" ::: "memory");

    // ---- phase 1: aggregate 16 nodes per warp into As ----
    for (int i = 0; i < 16; i++) {
        const int m = wid * 16 + i;
        const int node = row0 + m;

        float2 a0, a1;
        a0 = __half22float2(__ldg(&src2[(size_t)node * SRCW + lane]));
        a1 = make_float2(0.f, 0.f);
        if (SRCW == 64) {
            a1 = __half22float2(__ldg(&src2[(size_t)node * SRCW + 32 + lane]));
        } else if (lane < 8) {
            a1 = __half22float2(__ldg(&src2[(size_t)node * SRCW + 32 + lane]));
        }

        int s0 = __ldg(&rowptr[node]);
        int s1 = __ldg(&rowptr[node + 1]);
        int e = s0;
        for (; e + 4 <= s1; e += 4) {
            int i0 = __ldg(&colidx[e + 0]);
            int i1 = __ldg(&colidx[e + 1]);
            int i2 = __ldg(&colidx[e + 2]);
            int i3 = __ldg(&colidx[e + 3]);
            float2 u0 = __half22float2(__ldg(&src2[(size_t)i0 * SRCW + lane]));
            float2 u1 = __half22float2(__ldg(&src2[(size_t)i1 * SRCW + lane]));
            float2 u2 = __half22float2(__ldg(&src2[(size_t)i2 * SRCW + lane]));
            float2 u3 = __half22float2(__ldg(&src2[(size_t)i3 * SRCW + lane]));
            a0.x += u0.x + u1.x + u2.x + u3.x;
            a0.y += u0.y + u1.y + u2.y + u3.y;
            if (SRCW == 64 || lane < 8) {
                float2 t0 = __half22float2(__ldg(&src2[(size_t)i0 * SRCW + 32 + lane]));
                float2 t1 = __half22float2(__ldg(&src2[(size_t)i1 * SRCW + 32 + lane]));
                float2 t2 = __half22float2(__ldg(&src2[(size_t)i2 * SRCW + 32 + lane]));
                float2 t3 = __half22float2(__ldg(&src2[(size_t)i3 * SRCW + 32 + lane]));
                a1.x += t0.x + t1.x + t2.x + t3.x;
                a1.y += t0.y + t1.y + t2.y + t3.y;
            }
        }
        for (; e < s1; e++) {
            int s = __ldg(&colidx[e]);
            float2 u0 = __half22float2(__ldg(&src2[(size_t)s * SRCW + lane]));
            a0.x += u0.x; a0.y += u0.y;
            if (SRCW == 64 || lane < 8) {
                float2 t0 = __half22float2(__ldg(&src2[(size_t)s * SRCW + 32 + lane]));
                a1.x += t0.x; a1.y += t0.y;
            }
        }

        float dd = __ldg(&dinv[node]);
        __half2* arow = reinterpret_cast<__half2*>(&As[m * ASTR]);   // ASTR even
        arow[lane] = __floats2half2_rn(a0.x * dd, a0.y * dd);
        if (SRCW == 64) {
            arow[32 + lane] = __floats2half2_rn(a1.x * dd, a1.y * dd);
        } else if (lane < 8) {
            arow[32 + lane] = __floats2half2_rn(a1.x * dd, a1.y * dd);
            arow[40 + lane] = __floats2half2_rn(0.f, 0.f);   // pad halves 80..95
        }
    }

    asm volatile("cp.async.wait_group 0;" ::: "memory");
    __syncthreads();

    // ---- phase 2: MMA ----
    const int gid = lane >> 2;
    const int tig = lane & 3;
    const int wm  = (wid & 1) * 64;
    const int wn  = (wid >> 1) * 32;

    float c[4][4][4];
#pragma unroll
    for (int i = 0; i < 4; i++)
#pragma unroll
        for (int j = 0; j < 4; j++)
#pragma unroll
            for (int r = 0; r < 4; r++) c[i][j][r] = 0.0f;

#pragma unroll
    for (int kc = 0; kc < KH / 32; kc++) {
#pragma unroll
        for (int s = 0; s < 2; s++) {
            const int ks = kc * 32 + s * 16;
            uint32_t a[4][4];
#pragma unroll
            for (int mf = 0; mf < 4; mf++) {
                const __half* ab = &As[(wm + mf * 16 + gid) * ASTR + ks];
                a[mf][0] = *reinterpret_cast<const uint32_t*>(&ab[2 * tig]);
                a[mf][1] = *reinterpret_cast<const uint32_t*>(&ab[8 * ASTR + 2 * tig]);
                a[mf][2] = *reinterpret_cast<const uint32_t*>(&ab[2 * tig + 8]);
                a[mf][3] = *reinterpret_cast<const uint32_t*>(&ab[8 * ASTR + 2 * tig + 8]);
            }
            uint32_t b[4][2];
#pragma unroll
            for (int nf = 0; nf < 4; nf++) {
                const __half* bb = &Bs[(wn + nf * 8 + gid) * ASTR + ks];
                b[nf][0] = *reinterpret_cast<const uint32_t*>(&bb[2 * tig]);
                b[nf][1] = *reinterpret_cast<const uint32_t*>(&bb[2 * tig + 8]);
            }
#pragma unroll
            for (int mf = 0; mf < 4; mf++)
#pragma unroll
                for (int nf = 0; nf < 4; nf++) {
                    asm volatile(
                        "mma.sync.aligned.m16n8k16.row.col.f32.f16.f16.f32 "
                        "{%0,%1,%2,%3}, {%4,%5,%6,%7}, {%8,%9}, {%0,%1,%2,%3};"
                        : "+f"(c[mf][nf][0]), "+f"(c[mf][nf][1]),
                          "+f"(c[mf][nf][2]), "+f"(c[mf][nf][3])
                        : "r"(a[mf][0]), "r"(a[mf][1]), "r"(a[mf][2]), "r"(a[mf][3]),
                          "r"(b[nf][0]), "r"(b[nf][1]));
                }
        }
    }

    // ---- epilogue ----
    float bxv[4], byv[4];
#pragma unroll
    for (int nf = 0; nf < 4; nf++) {
        const int cc = wn + nf * 8 + 2 * tig;
        bxv[nf] = bias[cc];
        byv[nf] = bias[cc + 1];
    }
#pragma unroll
    for (int mf = 0; mf < 4; mf++) {
        const int r0 = row0 + wm + mf * 16 + gid;
        float rs0 = 1.0f, rs1 = 1.0f;
        if (rowscale) { rs0 = rowscale[r0]; rs1 = rowscale[r0 + 8]; }
#pragma unroll
        for (int nf = 0; nf < 4; nf++) {
            const int cc = wn + nf * 8 + 2 * tig;
            __half2 v0 = __floats2half2_rn(fmaxf(c[mf][nf][0] + bxv[nf], 0.f) * rs0,
                                           fmaxf(c[mf][nf][1] + byv[nf], 0.f) * rs0);
            __half2 v1 = __floats2half2_rn(fmaxf(c[mf][nf][2] + bxv[nf], 0.f) * rs1,
                                           fmaxf(c[mf][nf][3] + byv[nf], 0.f) * rs1);
            *reinterpret_cast<__half2*>(&out[(size_t)r0 * 128 + cc]) = v0;
            *reinterpret_cast<__half2*>(&out[(size_t)(r0 + 8) * 128 + cc]) = v1;
        }
    }
}

// ---------------- FFMA GEMM for FF head (full fp32): out = relu(A@W + bias) ----------------
__global__ void __launch_bounds__(256, 2)
gemm_ff_kernel(const float* __restrict__ A, const float* __restrict__ W,
               const float* __restrict__ bias, float* __restrict__ out,
               int M, int K, int Nout)
{
    __shared__ float As[16 * 128];
    __shared__ float Bs[16 * 128];

    const int tid  = threadIdx.x;
    const int tx   = tid & 15;
    const int ty   = tid >> 4;
    const int row0 = blockIdx.x * 128;
    const int col0 = blockIdx.y * 128;

    float acc[8][8];
#pragma unroll
    for (int i = 0; i < 8; i++)
#pragma unroll
        for (int j = 0; j < 8; j++) acc[i][j] = 0.0f;

    const int KC = (K + 15) >> 4;
    for (int kc = 0; kc < KC; kc++) {
        const int k0 = kc << 4;
        for (int i = tid; i < 512; i += 256) {
            int m = i >> 2, kv = (i & 3) << 2;
            int row = row0 + m;
            float4 v = make_float4(0.f, 0.f, 0.f, 0.f);
            if (row < M && (k0 + kv) < K)
                v = *reinterpret_cast<const float4*>(&A[(size_t)row * K + k0 + kv]);
            As[(kv + 0) * 128 + m] = v.x;
            As[(kv + 1) * 128 + m] = v.y;
            As[(kv + 2) * 128 + m] = v.z;
            As[(kv + 3) * 128 + m] = v.w;
        }
        for (int i = tid; i < 512; i += 256) {
            int kk = i >> 5, n4 = (i & 31) << 2;
            float4 v = make_float4(0.f, 0.f, 0.f, 0.f);
            if ((k0 + kk) < K)
                v = *reinterpret_cast<const float4*>(&W[(size_t)(k0 + kk) * Nout + col0 + n4]);
            *reinterpret_cast<float4*>(&Bs[kk * 128 + n4]) = v;
        }
        __syncthreads();
#pragma unroll
        for (int kk = 0; kk < 16; kk++) {
            float4 a0 = *reinterpret_cast<const float4*>(&As[kk * 128 + ty * 8]);
            float4 a1 = *reinterpret_cast<const float4*>(&As[kk * 128 + ty * 8 + 4]);
            float4 b0 = *reinterpret_cast<const float4*>(&Bs[kk * 128 + tx * 8]);
            float4 b1 = *reinterpret_cast<const float4*>(&Bs[kk * 128 + tx * 8 + 4]);
            float av[8] = {a0.x, a0.y, a0.z, a0.w, a1.x, a1.y, a1.z, a1.w};
            float bv[8] = {b0.x, b0.y, b0.z, b0.w, b1.x, b1.y, b1.z, b1.w};
#pragma unroll
            for (int i = 0; i < 8; i++)
#pragma unroll
                for (int j = 0; j < 8; j++)
                    acc[i][j] += av[i] * bv[j];
        }
        __syncthreads();
    }

#pragma unroll
    for (int i = 0; i < 8; i++) {
        int row = row0 + ty * 8 + i;
        if (row >= M) break;
        const float4 b0 = *reinterpret_cast<const float4*>(&bias[col0 + tx * 8]);
        const float4 b1 = *reinterpret_cast<const float4*>(&bias[col0 + tx * 8 + 4]);
        float4 v0 = make_float4(fmaxf(acc[i][0] + b0.x, 0.f), fmaxf(acc[i][1] + b0.y, 0.f),
                                fmaxf(acc[i][2] + b0.z, 0.f), fmaxf(acc[i][3] + b0.w, 0.f));
        float4 v1 = make_float4(fmaxf(acc[i][4] + b1.x, 0.f), fmaxf(acc[i][5] + b1.y, 0.f),
                                fmaxf(acc[i][6] + b1.z, 0.f), fmaxf(acc[i][7] + b1.w, 0.f));
        float4* o = reinterpret_cast<float4*>(&out[(size_t)row * Nout + col0 + tx * 8]);
        o[0] = v0; o[1] = v1;
    }
}

// ---------------- global max pool over sorted batch ids (fp16 input, fp32 out) ----------------
__global__ void pool_kernel(const __half* __restrict__ h, const int* __restrict__ batch,
                            float* __restrict__ pool, int N)
{
    int g = blockIdx.x;
    int j = threadIdx.x;
    __shared__ int se[2];
    if (threadIdx.x < 2) {
        int target = g + threadIdx.x;
        int lo = 0, hi = N;
        while (lo < hi) {
            int mid = (lo + hi) >> 1;
            if (batch[mid] < target) lo = mid + 1; else hi = mid;
        }
        se[threadIdx.x] = lo;
    }
    __syncthreads();
    int start = se[0], end = se[1];
    float m = -3.402823466e38f;
    int i = start;
    for (; i + 2 <= end; i += 2) {
        float v0 = __half2float(__ldg(&h[(size_t)i * HD + j]));
        float v1 = __half2float(__ldg(&h[(size_t)(i + 1) * HD + j]));
        m = fmaxf(m, fmaxf(v0, v1));
    }
    if (i < end) m = fmaxf(m, __half2float(__ldg(&h[(size_t)i * HD + j])));
    pool[(size_t)g * HD + j] = m;
}

// ---------------- launch ----------------
extern "C" void kernel_launch(void* const* d_in, const int* in_sizes, int n_in,
                              void* d_out, int out_size)
{
    const float* x     = (const float*)d_in[0];
    const int*   ei    = (const int*)d_in[1];
    const int*   batch = (const int*)d_in[2];
    const float* W0    = (const float*)d_in[3];
    const float* b0    = (const float*)d_in[4];
    const float* W1    = (const float*)d_in[5];
    const float* b1    = (const float*)d_in[6];
    const float* Wf0   = (const float*)d_in[7];
    const float* bf0   = (const float*)d_in[8];
    const float* Wf1   = (const float*)d_in[9];
    const float* bf1   = (const float*)d_in[10];
    float*       out   = (float*)d_out;

    const int F_IN = 78;
    const int N = in_sizes[0] / F_IN;
    const int E = in_sizes[1] / 2;
    const int G = out_size / HD;

    const int* src = ei;
    const int* dst = ei + E;

    int *p_counts, *p_rowptr, *p_cursor, *p_colidx, *p_bsum, *p_boff;
    float *p_dinv, *p_pool, *p_ff;
    __half *p_xs, *p_hh, *p_h1, *p_w0t, *p_w1t;
    cudaGetSymbolAddress((void**)&p_counts, g_counts);
    cudaGetSymbolAddress((void**)&p_rowptr, g_rowptr);
    cudaGetSymbolAddress((void**)&p_cursor, g_cursor);
    cudaGetSymbolAddress((void**)&p_colidx, g_colidx);
    cudaGetSymbolAddress((void**)&p_bsum,   g_bsum);
    cudaGetSymbolAddress((void**)&p_boff,   g_boff);
    cudaGetSymbolAddress((void**)&p_dinv,   g_dinv);
    cudaGetSymbolAddress((void**)&p_xs,     g_xs);
    cudaGetSymbolAddress((void**)&p_hh,     g_hh);
    cudaGetSymbolAddress((void**)&p_h1,     g_h1);
    cudaGetSymbolAddress((void**)&p_w0t,    g_w0t);
    cudaGetSymbolAddress((void**)&p_w1t,    g_w1t);
    cudaGetSymbolAddress((void**)&p_pool,   g_pool);
    cudaGetSymbolAddress((void**)&p_ff,     g_ff);

    const int TB = 256;
    int gN = (N + TB - 1) / TB;
    int gE = (E + TB - 1) / TB;
    int NB = (N + CHUNK - 1) / CHUNK;

    // fused kernel smem sizes
    const int smem0 = 2 * 128 * (96 + 8)  * (int)sizeof(__half);   // 53248
    const int smem1 = 2 * 128 * (128 + 8) * (int)sizeof(__half);   // 69632
    cudaFuncSetAttribute(fused_agg_gemm<40, 96>,  cudaFuncAttributeMaxDynamicSharedMemorySize, smem0);
    cudaFuncSetAttribute(fused_agg_gemm<64, 128>, cudaFuncAttributeMaxDynamicSharedMemorySize, smem1);

    // ---- CSR build + norm ----
    zero_counts_kernel<<<gN, TB>>>(p_counts, N);
    count_deg_kernel<<<gE, TB>>>(dst, p_counts, E);
    dinv_kernel<<<gN, TB>>>(p_counts, p_dinv, N);
    scan_chunk_sum<<<NB, 256>>>(p_counts, p_bsum, N);
    scan_bsum<<<1, 512>>>(p_bsum, p_boff, NB);
    scan_final<<<NB, CHUNK>>>(p_counts, p_boff, p_rowptr, p_cursor, N);
    fill_csr_kernel<<<gE, TB>>>(src, dst, p_cursor, p_colidx, E);

    // ---- conversions (xs = x * dinv) ----
    conv_x_kernel<<<(N * 40 + TB - 1) / TB, TB>>>(x, p_dinv, (__half2*)p_xs, N);
    conv_w0t_kernel<<<(128 * 96 + TB - 1) / TB, TB>>>(W0, p_w0t);
    conv_w1t_kernel<<<(128 * 128 + TB - 1) / TB, TB>>>(W1, p_w1t);

    // ---- layer 0 fused: hh = relu(agg(xs)@W0 + b0) * dinv ----
    fused_agg_gemm<40, 96><<<N / 128, TB, smem0>>>(
        (const __half2*)p_xs, p_rowptr, p_colidx, p_dinv, p_w0t, b0, p_dinv, p_hh);

    // ---- layer 1 fused: h1 = relu(agg(hh)@W1 + b1) ----
    fused_agg_gemm<64, 128><<<N / 128, TB, smem1>>>(
        (const __half2*)p_hh, p_rowptr, p_colidx, p_dinv, p_w1t, b1, nullptr, p_h1);

    // ---- pool + FF head (fp32) ----
    pool_kernel<<<G, HD>>>(p_h1, batch, p_pool, N);
    {
        dim3 grid((G + 127) / 128, 2);
        gemm_ff_kernel<<<grid, TB>>>(p_pool, Wf0, bf0, p_ff, G, HD, 256);
    }
    {
        dim3 grid((G + 127) / 128, 1);
        gemm_ff_kernel<<<grid, TB>>>(p_ff, Wf1, bf1, out, G, 256, HD);
    }
}

// round 9
// speedup vs baseline: 1.4597x; 1.4597x over previous
#include <cuda_runtime.h>
#include <cuda_fp16.h>
#include <cstdint>

#define NMAX 400000
#define EMAX 1600000
#define GMAX 4096
#define HD   128
#define CHUNK 1024

#define APAD 40    // smem row stride in halves (32 data + 8 pad)

// -------- device scratch --------
__device__ int    g_counts [NMAX];
__device__ int    g_rowptr [NMAX + 1];
__device__ int    g_cursor [NMAX];
__device__ int    g_colidx [EMAX];
__device__ int    g_bsum   [512];
__device__ int    g_boff   [512];
__device__ float  g_dinv   [NMAX];
__device__ __half g_xs     [(size_t)NMAX * 80];    // x*dinv fp16, stride 80 (cols 78,79 = 0)
__device__ __half g_ax     [(size_t)NMAX * 96];    // layer-0 agg out, stride 96 (cols 78..95 = 0)
__device__ __half g_hh     [(size_t)NMAX * 128];   // h0*dinv after layer0 GEMM; h1 after layer1 GEMM
__device__ __half g_ah     [(size_t)NMAX * 128];   // layer-1 agg out
__device__ __half g_w0t    [128 * 96];             // W0^T fp16 [n][k], k padded to 96
__device__ __half g_w1t    [128 * 128];            // W1^T fp16 [n][k]
__device__ float  g_pool   [(size_t)GMAX * HD];
__device__ float  g_ff     [(size_t)GMAX * 256];

// unpack uint2 (4 halves) and accumulate into float4
__device__ __forceinline__ void acc_u2(uint2 v, float4& a) {
    float2 f0 = __half22float2(*reinterpret_cast<__half2*>(&v.x));
    float2 f1 = __half22float2(*reinterpret_cast<__half2*>(&v.y));
    a.x += f0.x; a.y += f0.y; a.z += f1.x; a.w += f1.y;
}

__device__ __forceinline__ uint2 pack_f4(float4 a, float s) {
    uint2 o;
    __half2 h0 = __floats2half2_rn(a.x * s, a.y * s);
    __half2 h1 = __floats2half2_rn(a.z * s, a.w * s);
    o.x = *reinterpret_cast<uint32_t*>(&h0);
    o.y = *reinterpret_cast<uint32_t*>(&h1);
    return o;
}

// ---------------- degree / CSR build ----------------
__global__ void zero_counts_kernel(int* counts, int N) {
    int i = blockIdx.x * blockDim.x + threadIdx.x;
    if (i < N) counts[i] = 0;
}

__global__ void count_deg_kernel(const int* __restrict__ dst, int* counts, int E) {
    int e = blockIdx.x * blockDim.x + threadIdx.x;
    if (e < E) atomicAdd(&counts[dst[e]], 1);
}

__global__ void dinv_kernel(const int* __restrict__ counts, float* dinv, int N) {
    int i = blockIdx.x * blockDim.x + threadIdx.x;
    if (i < N) dinv[i] = rsqrtf((float)counts[i] + 1.0f);
}

__global__ void scan_chunk_sum(const int* __restrict__ counts, int* bsum, int N) {
    __shared__ int sh[256];
    int base = blockIdx.x * CHUNK;
    int s = 0;
    for (int i = threadIdx.x; i < CHUNK; i += 256) {
        int g = base + i;
        s += (g < N) ? counts[g] : 0;
    }
    sh[threadIdx.x] = s; __syncthreads();
    for (int o = 128; o > 0; o >>= 1) {
        if (threadIdx.x < o) sh[threadIdx.x] += sh[threadIdx.x + o];
        __syncthreads();
    }
    if (threadIdx.x == 0) bsum[blockIdx.x] = sh[0];
}

__global__ void scan_bsum(const int* __restrict__ bsum, int* boff, int NB) {
    __shared__ int sh[512];
    int v = (threadIdx.x < NB) ? bsum[threadIdx.x] : 0;
    sh[threadIdx.x] = v; __syncthreads();
    for (int o = 1; o < 512; o <<= 1) {
        int t = (threadIdx.x >= o) ? sh[threadIdx.x - o] : 0;
        __syncthreads();
        sh[threadIdx.x] += t;
        __syncthreads();
    }
    if (threadIdx.x < NB) boff[threadIdx.x] = sh[threadIdx.x] - v;  // exclusive
}

__global__ void scan_final(const int* __restrict__ counts, const int* __restrict__ boff,
                           int* rowptr, int* cursor, int N) {
    __shared__ int sh[CHUNK];
    int g = blockIdx.x * CHUNK + threadIdx.x;
    int v = (g < N) ? counts[g] : 0;
    sh[threadIdx.x] = v; __syncthreads();
    for (int o = 1; o < CHUNK; o <<= 1) {
        int t = (threadIdx.x >= o) ? sh[threadIdx.x - o] : 0;
        __syncthreads();
        sh[threadIdx.x] += t;
        __syncthreads();
    }
    if (g < N) {
        int excl = boff[blockIdx.x] + sh[threadIdx.x] - v;
        rowptr[g] = excl;
        cursor[g] = excl;
        if (g == N - 1) rowptr[N] = boff[blockIdx.x] + sh[threadIdx.x];
    }
}

__global__ void fill_csr_kernel(const int* __restrict__ src, const int* __restrict__ dst,
                                int* cursor, int* colidx, int E) {
    int e = blockIdx.x * blockDim.x + threadIdx.x;
    if (e < E) {
        int d = dst[e];
        int p = atomicAdd(&cursor[d], 1);
        colidx[p] = src[e];
    }
}

// ---------------- conversions ----------------
__global__ void conv_x_kernel(const float* __restrict__ x, const float* __restrict__ dinv,
                              __half2* __restrict__ xs2, int N) {
    int i = blockIdx.x * blockDim.x + threadIdx.x;   // over N*40 half2
    if (i >= N * 40) return;
    int n = i / 40;
    int c = i - n * 40;
    float dd = __ldg(&dinv[n]);
    float v0 = (2 * c     < 78) ? x[(size_t)n * 78 + 2 * c]     * dd : 0.0f;
    float v1 = (2 * c + 1 < 78) ? x[(size_t)n * 78 + 2 * c + 1] * dd : 0.0f;
    xs2[i] = __floats2half2_rn(v0, v1);
}

__global__ void conv_w0t_kernel(const float* __restrict__ W0, __half* __restrict__ W0t) {
    int i = blockIdx.x * blockDim.x + threadIdx.x;   // 128*96
    if (i >= 128 * 96) return;
    int n = i / 96;
    int k = i - n * 96;
    W0t[i] = (k < 78) ? __float2half_rn(W0[(size_t)k * 128 + n]) : __float2half_rn(0.0f);
}

__global__ void conv_w1t_kernel(const float* __restrict__ W1, __half* __restrict__ W1t) {
    int i = blockIdx.x * blockDim.x + threadIdx.x;   // 128*128
    if (i >= 128 * 128) return;
    int n = i >> 7;
    int k = i & 127;
    W1t[i] = __float2half_rn(W1[(size_t)k * 128 + n]);
}

// ---------------- agg0: ax[d] = h16( dinv[d]*(xs[d] + sum_{s} xs[s]) ), xs already *dinv ----------------
// xs row = 20 uint2 (160 B); lane < 20 owns one uint2 (4 halves). Output row = 24 uint2.
__global__ void agg0_kernel(const uint2* __restrict__ xsv, const int* __restrict__ rowptr,
                            const int* __restrict__ colidx, const float* __restrict__ dinv,
                            uint2* __restrict__ axv, int N)
{
    int w = (blockIdx.x * blockDim.x + threadIdx.x) >> 5;
    int lane = threadIdx.x & 31;
    if (w >= N) return;
    const bool act = lane < 20;

    float4 a = make_float4(0.f, 0.f, 0.f, 0.f);
    if (act) acc_u2(__ldg(&xsv[(size_t)w * 20 + lane]), a);

    int s0 = __ldg(&rowptr[w]);
    int s1 = __ldg(&rowptr[w + 1]);
    int e = s0;
    for (; e + 4 <= s1; e += 4) {
        int i0 = __ldg(&colidx[e + 0]);
        int i1 = __ldg(&colidx[e + 1]);
        int i2 = __ldg(&colidx[e + 2]);
        int i3 = __ldg(&colidx[e + 3]);
        if (act) {
            uint2 u0 = __ldg(&xsv[(size_t)i0 * 20 + lane]);
            uint2 u1 = __ldg(&xsv[(size_t)i1 * 20 + lane]);
            uint2 u2 = __ldg(&xsv[(size_t)i2 * 20 + lane]);
            uint2 u3 = __ldg(&xsv[(size_t)i3 * 20 + lane]);
            acc_u2(u0, a); acc_u2(u1, a); acc_u2(u2, a); acc_u2(u3, a);
        }
    }
    for (; e < s1; e++) {
        int s = __ldg(&colidx[e]);
        if (act) acc_u2(__ldg(&xsv[(size_t)s * 20 + lane]), a);
    }

    float dd = __ldg(&dinv[w]);
    if (act)
        axv[(size_t)w * 24 + lane] = pack_f4(a, dd);
    else if (lane < 24)
        axv[(size_t)w * 24 + lane] = make_uint2(0u, 0u);   // pad halves 80..95
}

// ---------------- agg1 (128-dim): ah[d] = h16( dinv[d]*(hs[d] + sum_{s} hs[s]) ), hs = h0*dinv ----------------
// hs row = 32 uint2 (256 B); each lane owns one uint2.
__global__ void agg1_kernel(const uint2* __restrict__ hsv, const int* __restrict__ rowptr,
                            const int* __restrict__ colidx, const float* __restrict__ dinv,
                            uint2* __restrict__ ahv, int N)
{
    int w = (blockIdx.x * blockDim.x + threadIdx.x) >> 5;
    int lane = threadIdx.x & 31;
    if (w >= N) return;

    float4 a = make_float4(0.f, 0.f, 0.f, 0.f);
    acc_u2(__ldg(&hsv[(size_t)w * 32 + lane]), a);

    int s0 = __ldg(&rowptr[w]);
    int s1 = __ldg(&rowptr[w + 1]);
    int e = s0;
    for (; e + 4 <= s1; e += 4) {
        int i0 = __ldg(&colidx[e + 0]);
        int i1 = __ldg(&colidx[e + 1]);
        int i2 = __ldg(&colidx[e + 2]);
        int i3 = __ldg(&colidx[e + 3]);
        uint2 u0 = __ldg(&hsv[(size_t)i0 * 32 + lane]);
        uint2 u1 = __ldg(&hsv[(size_t)i1 * 32 + lane]);
        uint2 u2 = __ldg(&hsv[(size_t)i2 * 32 + lane]);
        uint2 u3 = __ldg(&hsv[(size_t)i3 * 32 + lane]);
        acc_u2(u0, a); acc_u2(u1, a); acc_u2(u2, a); acc_u2(u3, a);
    }
    for (; e < s1; e++) {
        int s = __ldg(&colidx[e]);
        acc_u2(__ldg(&hsv[(size_t)s * 32 + lane]), a);
    }

    float dd = __ldg(&dinv[w]);
    ahv[(size_t)w * 32 + lane] = pack_f4(a, dd);
}

// ---------------- fp16 tensor-core GEMM: out = h16(relu(A@Wt^T + bias) [* rowscale]) ----------------
// A fp16 [M, K], Wt fp16 [128, K] (n-major), out fp16 [M, 128]
// block 256 (8 warps), tile 128x128, warp tile 64x32, mma.m16n8k16.f16.f16.f32
// M % 128 == 0, K % 32 == 0
__global__ void __launch_bounds__(256, 2)
gemm_h_kernel(const __half* __restrict__ A, const __half* __restrict__ Wt,
              const float* __restrict__ bias, const float* __restrict__ rowscale,
              __half* __restrict__ out, int K)
{
    __shared__ __half As[2][128 * APAD];
    __shared__ __half Bs[2][128 * APAD];

    const int tid  = threadIdx.x;
    const int row0 = blockIdx.x * 128;
    const int lane = tid & 31;
    const int wid  = tid >> 5;
    const int gid  = lane >> 2;
    const int tig  = lane & 3;
    const int wm   = (wid & 1) * 64;
    const int wn   = (wid >> 1) * 32;

    float c[4][4][4];
#pragma unroll
    for (int i = 0; i < 4; i++)
#pragma unroll
        for (int j = 0; j < 4; j++)
#pragma unroll
            for (int r = 0; r < 4; r++) c[i][j][r] = 0.0f;

    const int KC = K >> 5;   // 32 halves per tile

    auto issue = [&](int kc, int buf) {
        const int k0 = kc << 5;
#pragma unroll
        for (int rpt = 0; rpt < 2; rpt++) {
            int i = tid + rpt * 256;
            int m = i >> 2, ch = i & 3;
            const __half* src = A + (size_t)(row0 + m) * K + k0 + ch * 8;
            uint32_t dst = (uint32_t)__cvta_generic_to_shared(&As[buf][m * APAD + ch * 8]);
            asm volatile("cp.async.cg.shared.global [%0], [%1], 16;" :: "r"(dst), "l"(src));
        }
#pragma unroll
        for (int rpt = 0; rpt < 2; rpt++) {
            int i = tid + rpt * 256;
            int n = i >> 2, ch = i & 3;
            const __half* src = Wt + (size_t)n * K + k0 + ch * 8;
            uint32_t dst = (uint32_t)__cvta_generic_to_shared(&Bs[buf][n * APAD + ch * 8]);
            asm volatile("cp.async.cg.shared.global [%0], [%1], 16;" :: "r"(dst), "l"(src));
        }
        asm volatile("cp.async.commit_group;" ::: "memory");
    };

    issue(0, 0);

    for (int kc = 0; kc < KC; kc++) {
        const int buf = kc & 1;
        asm volatile("cp.async.wait_group 0;" ::: "memory");
        __syncthreads();
        if (kc + 1 < KC) issue(kc + 1, buf ^ 1);

#pragma unroll
        for (int s = 0; s < 2; s++) {
            const int ks = s * 16;
            uint32_t a[4][4];
#pragma unroll
            for (int mf = 0; mf < 4; mf++) {
                const __half* ab = &As[buf][(wm + mf * 16 + gid) * APAD + ks];
                a[mf][0] = *reinterpret_cast<const uint32_t*>(&ab[2 * tig]);
                a[mf][1] = *reinterpret_cast<const uint32_t*>(&ab[8 * APAD + 2 * tig]);
                a[mf][2] = *reinterpret_cast<const uint32_t*>(&ab[2 * tig + 8]);
                a[mf][3] = *reinterpret_cast<const uint32_t*>(&ab[8 * APAD + 2 * tig + 8]);
            }
            uint32_t b[4][2];
#pragma unroll
            for (int nf = 0; nf < 4; nf++) {
                const __half* bb = &Bs[buf][(wn + nf * 8 + gid) * APAD + ks];
                b[nf][0] = *reinterpret_cast<const uint32_t*>(&bb[2 * tig]);
                b[nf][1] = *reinterpret_cast<const uint32_t*>(&bb[2 * tig + 8]);
            }
#pragma unroll
            for (int mf = 0; mf < 4; mf++)
#pragma unroll
                for (int nf = 0; nf < 4; nf++) {
                    asm volatile(
                        "mma.sync.aligned.m16n8k16.row.col.f32.f16.f16.f32 "
                        "{%0,%1,%2,%3}, {%4,%5,%6,%7}, {%8,%9}, {%0,%1,%2,%3};"
                        : "+f"(c[mf][nf][0]), "+f"(c[mf][nf][1]),
                          "+f"(c[mf][nf][2]), "+f"(c[mf][nf][3])
                        : "r"(a[mf][0]), "r"(a[mf][1]), "r"(a[mf][2]), "r"(a[mf][3]),
                          "r"(b[nf][0]), "r"(b[nf][1]));
                }
        }
        __syncthreads();
    }

    // epilogue: bias + relu (+ optional row scale) -> fp16 half2 stores
    float bxv[4], byv[4];
#pragma unroll
    for (int nf = 0; nf < 4; nf++) {
        const int cc = wn + nf * 8 + 2 * tig;
        bxv[nf] = bias[cc];
        byv[nf] = bias[cc + 1];
    }
#pragma unroll
    for (int mf = 0; mf < 4; mf++) {
        const int r0 = row0 + wm + mf * 16 + gid;
        float rs0 = 1.0f, rs1 = 1.0f;
        if (rowscale) { rs0 = rowscale[r0]; rs1 = rowscale[r0 + 8]; }
#pragma unroll
        for (int nf = 0; nf < 4; nf++) {
            const int cc = wn + nf * 8 + 2 * tig;
            __half2 v0 = __floats2half2_rn(fmaxf(c[mf][nf][0] + bxv[nf], 0.f) * rs0,
                                           fmaxf(c[mf][nf][1] + byv[nf], 0.f) * rs0);
            __half2 v1 = __floats2half2_rn(fmaxf(c[mf][nf][2] + bxv[nf], 0.f) * rs1,
                                           fmaxf(c[mf][nf][3] + byv[nf], 0.f) * rs1);
            *reinterpret_cast<__half2*>(&out[(size_t)r0 * 128 + cc]) = v0;
            *reinterpret_cast<__half2*>(&out[(size_t)(r0 + 8) * 128 + cc]) = v1;
        }
    }
}

// ---------------- FFMA GEMM for FF head (full fp32): out = relu(A@W + bias) ----------------
__global__ void __launch_bounds__(256, 2)
gemm_ff_kernel(const float* __restrict__ A, const float* __restrict__ W,
               const float* __restrict__ bias, float* __restrict__ out,
               int M, int K, int Nout)
{
    __shared__ float As[16 * 128];
    __shared__ float Bs[16 * 128];

    const int tid  = threadIdx.x;
    const int tx   = tid & 15;
    const int ty   = tid >> 4;
    const int row0 = blockIdx.x * 128;
    const int col0 = blockIdx.y * 128;

    float acc[8][8];
#pragma unroll
    for (int i = 0; i < 8; i++)
#pragma unroll
        for (int j = 0; j < 8; j++) acc[i][j] = 0.0f;

    const int KC = (K + 15) >> 4;
    for (int kc = 0; kc < KC; kc++) {
        const int k0 = kc << 4;
        for (int i = tid; i < 512; i += 256) {
            int m = i >> 2, kv = (i & 3) << 2;
            int row = row0 + m;
            float4 v = make_float4(0.f, 0.f, 0.f, 0.f);
            if (row < M && (k0 + kv) < K)
                v = *reinterpret_cast<const float4*>(&A[(size_t)row * K + k0 + kv]);
            As[(kv + 0) * 128 + m] = v.x;
            As[(kv + 1) * 128 + m] = v.y;
            As[(kv + 2) * 128 + m] = v.z;
            As[(kv + 3) * 128 + m] = v.w;
        }
        for (int i = tid; i < 512; i += 256) {
            int kk = i >> 5, n4 = (i & 31) << 2;
            float4 v = make_float4(0.f, 0.f, 0.f, 0.f);
            if ((k0 + kk) < K)
                v = *reinterpret_cast<const float4*>(&W[(size_t)(k0 + kk) * Nout + col0 + n4]);
            *reinterpret_cast<float4*>(&Bs[kk * 128 + n4]) = v;
        }
        __syncthreads();
#pragma unroll
        for (int kk = 0; kk < 16; kk++) {
            float4 a0 = *reinterpret_cast<const float4*>(&As[kk * 128 + ty * 8]);
            float4 a1 = *reinterpret_cast<const float4*>(&As[kk * 128 + ty * 8 + 4]);
            float4 b0 = *reinterpret_cast<const float4*>(&Bs[kk * 128 + tx * 8]);
            float4 b1 = *reinterpret_cast<const float4*>(&Bs[kk * 128 + tx * 8 + 4]);
            float av[8] = {a0.x, a0.y, a0.z, a0.w, a1.x, a1.y, a1.z, a1.w};
            float bv[8] = {b0.x, b0.y, b0.z, b0.w, b1.x, b1.y, b1.z, b1.w};
#pragma unroll
            for (int i = 0; i < 8; i++)
#pragma unroll
                for (int j = 0; j < 8; j++)
                    acc[i][j] += av[i] * bv[j];
        }
        __syncthreads();
    }

#pragma unroll
    for (int i = 0; i < 8; i++) {
        int row = row0 + ty * 8 + i;
        if (row >= M) break;
        const float4 b0 = *reinterpret_cast<const float4*>(&bias[col0 + tx * 8]);
        const float4 b1 = *reinterpret_cast<const float4*>(&bias[col0 + tx * 8 + 4]);
        float4 v0 = make_float4(fmaxf(acc[i][0] + b0.x, 0.f), fmaxf(acc[i][1] + b0.y, 0.f),
                                fmaxf(acc[i][2] + b0.z, 0.f), fmaxf(acc[i][3] + b0.w, 0.f));
        float4 v1 = make_float4(fmaxf(acc[i][4] + b1.x, 0.f), fmaxf(acc[i][5] + b1.y, 0.f),
                                fmaxf(acc[i][6] + b1.z, 0.f), fmaxf(acc[i][7] + b1.w, 0.f));
        float4* o = reinterpret_cast<float4*>(&out[(size_t)row * Nout + col0 + tx * 8]);
        o[0] = v0; o[1] = v1;
    }
}

// ---------------- global max pool over sorted batch ids (fp16 input, fp32 out) ----------------
__global__ void pool_kernel(const __half* __restrict__ h, const int* __restrict__ batch,
                            float* __restrict__ pool, int N)
{
    int g = blockIdx.x;
    int j = threadIdx.x;
    __shared__ int se[2];
    if (threadIdx.x < 2) {
        int target = g + threadIdx.x;
        int lo = 0, hi = N;
        while (lo < hi) {
            int mid = (lo + hi) >> 1;
            if (batch[mid] < target) lo = mid + 1; else hi = mid;
        }
        se[threadIdx.x] = lo;
    }
    __syncthreads();
    int start = se[0], end = se[1];
    float m = -3.402823466e38f;
    int i = start;
    for (; i + 2 <= end; i += 2) {
        float v0 = __half2float(__ldg(&h[(size_t)i * HD + j]));
        float v1 = __half2float(__ldg(&h[(size_t)(i + 1) * HD + j]));
        m = fmaxf(m, fmaxf(v0, v1));
    }
    if (i < end) m = fmaxf(m, __half2float(__ldg(&h[(size_t)i * HD + j])));
    pool[(size_t)g * HD + j] = m;
}

// ---------------- launch ----------------
extern "C" void kernel_launch(void* const* d_in, const int* in_sizes, int n_in,
                              void* d_out, int out_size)
{
    const float* x     = (const float*)d_in[0];
    const int*   ei    = (const int*)d_in[1];
    const int*   batch = (const int*)d_in[2];
    const float* W0    = (const float*)d_in[3];
    const float* b0    = (const float*)d_in[4];
    const float* W1    = (const float*)d_in[5];
    const float* b1    = (const float*)d_in[6];
    const float* Wf0   = (const float*)d_in[7];
    const float* bf0   = (const float*)d_in[8];
    const float* Wf1   = (const float*)d_in[9];
    const float* bf1   = (const float*)d_in[10];
    float*       out   = (float*)d_out;

    const int F_IN = 78;
    const int N = in_sizes[0] / F_IN;
    const int E = in_sizes[1] / 2;
    const int G = out_size / HD;

    const int* src = ei;
    const int* dst = ei + E;

    int *p_counts, *p_rowptr, *p_cursor, *p_colidx, *p_bsum, *p_boff;
    float *p_dinv, *p_pool, *p_ff;
    __half *p_xs, *p_ax, *p_hh, *p_ah, *p_w0t, *p_w1t;
    cudaGetSymbolAddress((void**)&p_counts, g_counts);
    cudaGetSymbolAddress((void**)&p_rowptr, g_rowptr);
    cudaGetSymbolAddress((void**)&p_cursor, g_cursor);
    cudaGetSymbolAddress((void**)&p_colidx, g_colidx);
    cudaGetSymbolAddress((void**)&p_bsum,   g_bsum);
    cudaGetSymbolAddress((void**)&p_boff,   g_boff);
    cudaGetSymbolAddress((void**)&p_dinv,   g_dinv);
    cudaGetSymbolAddress((void**)&p_xs,     g_xs);
    cudaGetSymbolAddress((void**)&p_ax,     g_ax);
    cudaGetSymbolAddress((void**)&p_hh,     g_hh);
    cudaGetSymbolAddress((void**)&p_ah,     g_ah);
    cudaGetSymbolAddress((void**)&p_w0t,    g_w0t);
    cudaGetSymbolAddress((void**)&p_w1t,    g_w1t);
    cudaGetSymbolAddress((void**)&p_pool,   g_pool);
    cudaGetSymbolAddress((void**)&p_ff,     g_ff);

    const int TB = 256;
    int gN = (N + TB - 1) / TB;
    int gE = (E + TB - 1) / TB;
    int NB = (N + CHUNK - 1) / CHUNK;
    int gW = (N * 32 + TB - 1) / TB;   // warp-per-node grids

    // ---- CSR build + norm ----
    zero_counts_kernel<<<gN, TB>>>(p_counts, N);
    count_deg_kernel<<<gE, TB>>>(dst, p_counts, E);
    dinv_kernel<<<gN, TB>>>(p_counts, p_dinv, N);
    scan_chunk_sum<<<NB, 256>>>(p_counts, p_bsum, N);
    scan_bsum<<<1, 512>>>(p_bsum, p_boff, NB);
    scan_final<<<NB, CHUNK>>>(p_counts, p_boff, p_rowptr, p_cursor, N);
    fill_csr_kernel<<<gE, TB>>>(src, dst, p_cursor, p_colidx, E);

    // ---- conversions (xs = x * dinv) ----
    conv_x_kernel<<<(N * 40 + TB - 1) / TB, TB>>>(x, p_dinv, (__half2*)p_xs, N);
    conv_w0t_kernel<<<(128 * 96 + TB - 1) / TB, TB>>>(W0, p_w0t);
    conv_w1t_kernel<<<(128 * 128 + TB - 1) / TB, TB>>>(W1, p_w1t);

    // ---- layer 0: aggregate-then-transform; GEMM stores h0*dinv ----
    agg0_kernel<<<gW, TB>>>((const uint2*)p_xs, p_rowptr, p_colidx, p_dinv, (uint2*)p_ax, N);
    gemm_h_kernel<<<N / 128, TB>>>(p_ax, p_w0t, b0, p_dinv, p_hh, 96);

    // ---- layer 1 (GEMM stores plain h1 for pooling) ----
    agg1_kernel<<<gW, TB>>>((const uint2*)p_hh, p_rowptr, p_colidx, p_dinv, (uint2*)p_ah, N);
    gemm_h_kernel<<<N / 128, TB>>>(p_ah, p_w1t, b1, nullptr, p_hh, 128);

    // ---- pool + FF head (fp32) ----
    pool_kernel<<<G, HD>>>(p_hh, batch, p_pool, N);
    {
        dim3 grid((G + 127) / 128, 2);
        gemm_ff_kernel<<<grid, TB>>>(p_pool, Wf0, bf0, p_ff, G, HD, 256);
    }
    {
        dim3 grid((G + 127) / 128, 1);
        gemm_ff_kernel<<<grid, TB>>>(p_ff, Wf1, bf1, out, G, 256, HD);
    }
}

// round 10
// speedup vs baseline: 1.5129x; 1.0365x over previous
#include <cuda_runtime.h>
#include <cuda_fp16.h>
#include <cstdint>

#define NMAX 400000
#define EMAX 1600000
#define GMAX 4096
#define HD   128
#define CHUNK 1024

#define APAD 40    // smem row stride in halves (32 data + 8 pad)

// -------- device scratch --------
__device__ int    g_counts [NMAX];
__device__ int    g_rowptr [NMAX + 1];
__device__ int    g_cursor [NMAX];
__device__ int    g_colidx [EMAX];
__device__ int    g_bsum   [512];
__device__ int    g_boff   [512];
__device__ float  g_dinv   [NMAX];
__device__ __half g_xs     [(size_t)NMAX * 80];    // x*dinv fp16, stride 80 (cols 78,79 = 0)
__device__ __half g_ax     [(size_t)NMAX * 96];    // layer-0 agg out, stride 96 (cols 78..95 = 0)
__device__ __half g_hh     [(size_t)NMAX * 128];   // h0*dinv after layer0 GEMM
__device__ __half g_ah     [(size_t)NMAX * 128];   // layer-1 agg out
__device__ __half g_w0t    [128 * 96];             // W0^T fp16 [n][k], k padded to 96
__device__ __half g_w1t    [128 * 128];            // W1^T fp16 [n][k]
__device__ float  g_pool   [(size_t)GMAX * HD];
__device__ float  g_ff     [(size_t)GMAX * 256];

// unpack uint2 (4 halves) and accumulate into float4
__device__ __forceinline__ void acc_u2(uint2 v, float4& a) {
    float2 f0 = __half22float2(*reinterpret_cast<__half2*>(&v.x));
    float2 f1 = __half22float2(*reinterpret_cast<__half2*>(&v.y));
    a.x += f0.x; a.y += f0.y; a.z += f1.x; a.w += f1.y;
}

__device__ __forceinline__ uint2 pack_f4(float4 a, float s) {
    uint2 o;
    __half2 h0 = __floats2half2_rn(a.x * s, a.y * s);
    __half2 h1 = __floats2half2_rn(a.z * s, a.w * s);
    o.x = *reinterpret_cast<uint32_t*>(&h0);
    o.y = *reinterpret_cast<uint32_t*>(&h1);
    return o;
}

// ---------------- degree / CSR build ----------------
__global__ void count_deg_kernel(const int* __restrict__ dst, int* counts, int E) {
    int e = blockIdx.x * blockDim.x + threadIdx.x;
    if (e < E) atomicAdd(&counts[dst[e]], 1);
}

// chunk sums for scan + dinv computation (counts read once anyway)
__global__ void scan_chunk_sum(const int* __restrict__ counts, int* bsum,
                               float* __restrict__ dinv, int N) {
    __shared__ int sh[256];
    int base = blockIdx.x * CHUNK;
    int s = 0;
    for (int i = threadIdx.x; i < CHUNK; i += 256) {
        int g = base + i;
        int c = (g < N) ? counts[g] : 0;
        s += c;
        if (g < N) dinv[g] = rsqrtf((float)c + 1.0f);
    }
    sh[threadIdx.x] = s; __syncthreads();
    for (int o = 128; o > 0; o >>= 1) {
        if (threadIdx.x < o) sh[threadIdx.x] += sh[threadIdx.x + o];
        __syncthreads();
    }
    if (threadIdx.x == 0) bsum[blockIdx.x] = sh[0];
}

__global__ void scan_bsum(const int* __restrict__ bsum, int* boff, int NB) {
    __shared__ int sh[512];
    int v = (threadIdx.x < NB) ? bsum[threadIdx.x] : 0;
    sh[threadIdx.x] = v; __syncthreads();
    for (int o = 1; o < 512; o <<= 1) {
        int t = (threadIdx.x >= o) ? sh[threadIdx.x - o] : 0;
        __syncthreads();
        sh[threadIdx.x] += t;
        __syncthreads();
    }
    if (threadIdx.x < NB) boff[threadIdx.x] = sh[threadIdx.x] - v;  // exclusive
}

__global__ void scan_final(const int* __restrict__ counts, const int* __restrict__ boff,
                           int* rowptr, int* cursor, int N) {
    __shared__ int sh[CHUNK];
    int g = blockIdx.x * CHUNK + threadIdx.x;
    int v = (g < N) ? counts[g] : 0;
    sh[threadIdx.x] = v; __syncthreads();
    for (int o = 1; o < CHUNK; o <<= 1) {
        int t = (threadIdx.x >= o) ? sh[threadIdx.x - o] : 0;
        __syncthreads();
        sh[threadIdx.x] += t;
        __syncthreads();
    }
    if (g < N) {
        int excl = boff[blockIdx.x] + sh[threadIdx.x] - v;
        rowptr[g] = excl;
        cursor[g] = excl;
        if (g == N - 1) rowptr[N] = boff[blockIdx.x] + sh[threadIdx.x];
    }
}

__global__ void fill_csr_kernel(const int* __restrict__ src, const int* __restrict__ dst,
                                int* cursor, int* colidx, int E) {
    int e = blockIdx.x * blockDim.x + threadIdx.x;
    if (e < E) {
        int d = dst[e];
        int p = atomicAdd(&cursor[d], 1);
        colidx[p] = src[e];
    }
}

// ---------------- conversions ----------------
__global__ void conv_x_kernel(const float* __restrict__ x, const float* __restrict__ dinv,
                              __half2* __restrict__ xs2, int N) {
    int i = blockIdx.x * blockDim.x + threadIdx.x;   // over N*40 half2
    if (i >= N * 40) return;
    int n = i / 40;
    int c = i - n * 40;
    float dd = __ldg(&dinv[n]);
    float v0 = (2 * c     < 78) ? x[(size_t)n * 78 + 2 * c]     * dd : 0.0f;
    float v1 = (2 * c + 1 < 78) ? x[(size_t)n * 78 + 2 * c + 1] * dd : 0.0f;
    xs2[i] = __floats2half2_rn(v0, v1);
}

// combined weight transpose+convert: W0 [78,128]->W0t [128,96], W1 [128,128]->W1t [128,128]
__global__ void conv_w_kernel(const float* __restrict__ W0, const float* __restrict__ W1,
                              __half* __restrict__ W0t, __half* __restrict__ W1t) {
    int i = blockIdx.x * blockDim.x + threadIdx.x;
    if (i < 128 * 96) {
        int n = i / 96;
        int k = i - n * 96;
        W0t[i] = (k < 78) ? __float2half_rn(W0[(size_t)k * 128 + n]) : __float2half_rn(0.0f);
    } else if (i < 128 * 96 + 128 * 128) {
        int j = i - 128 * 96;
        int n = j >> 7;
        int k = j & 127;
        W1t[j] = __float2half_rn(W1[(size_t)k * 128 + n]);
    }
}

// ---------------- agg0: ax[d] = h16( dinv[d]*(xs[d] + sum_{s} xs[s]) ), xs already *dinv ----------------
__global__ void agg0_kernel(const uint2* __restrict__ xsv, const int* __restrict__ rowptr,
                            const int* __restrict__ colidx, const float* __restrict__ dinv,
                            uint2* __restrict__ axv, int N)
{
    int w = (blockIdx.x * blockDim.x + threadIdx.x) >> 5;
    int lane = threadIdx.x & 31;
    if (w >= N) return;
    const bool act = lane < 20;

    float4 a = make_float4(0.f, 0.f, 0.f, 0.f);
    if (act) acc_u2(__ldg(&xsv[(size_t)w * 20 + lane]), a);

    int s0 = __ldg(&rowptr[w]);
    int s1 = __ldg(&rowptr[w + 1]);
    int e = s0;
    for (; e + 4 <= s1; e += 4) {
        int i0 = __ldg(&colidx[e + 0]);
        int i1 = __ldg(&colidx[e + 1]);
        int i2 = __ldg(&colidx[e + 2]);
        int i3 = __ldg(&colidx[e + 3]);
        if (act) {
            uint2 u0 = __ldg(&xsv[(size_t)i0 * 20 + lane]);
            uint2 u1 = __ldg(&xsv[(size_t)i1 * 20 + lane]);
            uint2 u2 = __ldg(&xsv[(size_t)i2 * 20 + lane]);
            uint2 u3 = __ldg(&xsv[(size_t)i3 * 20 + lane]);
            acc_u2(u0, a); acc_u2(u1, a); acc_u2(u2, a); acc_u2(u3, a);
        }
    }
    for (; e < s1; e++) {
        int s = __ldg(&colidx[e]);
        if (act) acc_u2(__ldg(&xsv[(size_t)s * 20 + lane]), a);
    }

    float dd = __ldg(&dinv[w]);
    if (act)
        axv[(size_t)w * 24 + lane] = pack_f4(a, dd);
    else if (lane < 24)
        axv[(size_t)w * 24 + lane] = make_uint2(0u, 0u);   // pad halves 80..95
}

// ---------------- agg1 (128-dim): ah[d] = h16( dinv[d]*(hs[d] + sum_{s} hs[s]) ), hs = h0*dinv ----------------
__global__ void agg1_kernel(const uint2* __restrict__ hsv, const int* __restrict__ rowptr,
                            const int* __restrict__ colidx, const float* __restrict__ dinv,
                            uint2* __restrict__ ahv, int N)
{
    int w = (blockIdx.x * blockDim.x + threadIdx.x) >> 5;
    int lane = threadIdx.x & 31;
    if (w >= N) return;

    float4 a = make_float4(0.f, 0.f, 0.f, 0.f);
    acc_u2(__ldg(&hsv[(size_t)w * 32 + lane]), a);

    int s0 = __ldg(&rowptr[w]);
    int s1 = __ldg(&rowptr[w + 1]);
    int e = s0;
    for (; e + 4 <= s1; e += 4) {
        int i0 = __ldg(&colidx[e + 0]);
        int i1 = __ldg(&colidx[e + 1]);
        int i2 = __ldg(&colidx[e + 2]);
        int i3 = __ldg(&colidx[e + 3]);
        uint2 u0 = __ldg(&hsv[(size_t)i0 * 32 + lane]);
        uint2 u1 = __ldg(&hsv[(size_t)i1 * 32 + lane]);
        uint2 u2 = __ldg(&hsv[(size_t)i2 * 32 + lane]);
        uint2 u3 = __ldg(&hsv[(size_t)i3 * 32 + lane]);
        acc_u2(u0, a); acc_u2(u1, a); acc_u2(u2, a); acc_u2(u3, a);
    }
    for (; e < s1; e++) {
        int s = __ldg(&colidx[e]);
        acc_u2(__ldg(&hsv[(size_t)s * 32 + lane]), a);
    }

    float dd = __ldg(&dinv[w]);
    ahv[(size_t)w * 32 + lane] = pack_f4(a, dd);
}

// ---------------- fp16 tensor-core GEMM (layer 0): hh = h16(relu(A@Wt^T + bias) * rowscale) ----------------
__global__ void __launch_bounds__(256, 2)
gemm_h_kernel(const __half* __restrict__ A, const __half* __restrict__ Wt,
              const float* __restrict__ bias, const float* __restrict__ rowscale,
              __half* __restrict__ out, int K)
{
    __shared__ __half As[2][128 * APAD];
    __shared__ __half Bs[2][128 * APAD];

    const int tid  = threadIdx.x;
    const int row0 = blockIdx.x * 128;
    const int lane = tid & 31;
    const int wid  = tid >> 5;
    const int gid  = lane >> 2;
    const int tig  = lane & 3;
    const int wm   = (wid & 1) * 64;
    const int wn   = (wid >> 1) * 32;

    float c[4][4][4];
#pragma unroll
    for (int i = 0; i < 4; i++)
#pragma unroll
        for (int j = 0; j < 4; j++)
#pragma unroll
            for (int r = 0; r < 4; r++) c[i][j][r] = 0.0f;

    const int KC = K >> 5;

    auto issue = [&](int kc, int buf) {
        const int k0 = kc << 5;
#pragma unroll
        for (int rpt = 0; rpt < 2; rpt++) {
            int i = tid + rpt * 256;
            int m = i >> 2, ch = i & 3;
            const __half* src = A + (size_t)(row0 + m) * K + k0 + ch * 8;
            uint32_t dst = (uint32_t)__cvta_generic_to_shared(&As[buf][m * APAD + ch * 8]);
            asm volatile("cp.async.cg.shared.global [%0], [%1], 16;" :: "r"(dst), "l"(src));
        }
#pragma unroll
        for (int rpt = 0; rpt < 2; rpt++) {
            int i = tid + rpt * 256;
            int n = i >> 2, ch = i & 3;
            const __half* src = Wt + (size_t)n * K + k0 + ch * 8;
            uint32_t dst = (uint32_t)__cvta_generic_to_shared(&Bs[buf][n * APAD + ch * 8]);
            asm volatile("cp.async.cg.shared.global [%0], [%1], 16;" :: "r"(dst), "l"(src));
        }
        asm volatile("cp.async.commit_group;" ::: "memory");
    };

    issue(0, 0);

    for (int kc = 0; kc < KC; kc++) {
        const int buf = kc & 1;
        asm volatile("cp.async.wait_group 0;" ::: "memory");
        __syncthreads();
        if (kc + 1 < KC) issue(kc + 1, buf ^ 1);

#pragma unroll
        for (int s = 0; s < 2; s++) {
            const int ks = s * 16;
            uint32_t a[4][4];
#pragma unroll
            for (int mf = 0; mf < 4; mf++) {
                const __half* ab = &As[buf][(wm + mf * 16 + gid) * APAD + ks];
                a[mf][0] = *reinterpret_cast<const uint32_t*>(&ab[2 * tig]);
                a[mf][1] = *reinterpret_cast<const uint32_t*>(&ab[8 * APAD + 2 * tig]);
                a[mf][2] = *reinterpret_cast<const uint32_t*>(&ab[2 * tig + 8]);
                a[mf][3] = *reinterpret_cast<const uint32_t*>(&ab[8 * APAD + 2 * tig + 8]);
            }
            uint32_t b[4][2];
#pragma unroll
            for (int nf = 0; nf < 4; nf++) {
                const __half* bb = &Bs[buf][(wn + nf * 8 + gid) * APAD + ks];
                b[nf][0] = *reinterpret_cast<const uint32_t*>(&bb[2 * tig]);
                b[nf][1] = *reinterpret_cast<const uint32_t*>(&bb[2 * tig + 8]);
            }
#pragma unroll
            for (int mf = 0; mf < 4; mf++)
#pragma unroll
                for (int nf = 0; nf < 4; nf++) {
                    asm volatile(
                        "mma.sync.aligned.m16n8k16.row.col.f32.f16.f16.f32 "
                        "{%0,%1,%2,%3}, {%4,%5,%6,%7}, {%8,%9}, {%0,%1,%2,%3};"
                        : "+f"(c[mf][nf][0]), "+f"(c[mf][nf][1]),
                          "+f"(c[mf][nf][2]), "+f"(c[mf][nf][3])
                        : "r"(a[mf][0]), "r"(a[mf][1]), "r"(a[mf][2]), "r"(a[mf][3]),
                          "r"(b[nf][0]), "r"(b[nf][1]));
                }
        }
        __syncthreads();
    }

    float bxv[4], byv[4];
#pragma unroll
    for (int nf = 0; nf < 4; nf++) {
        const int cc = wn + nf * 8 + 2 * tig;
        bxv[nf] = bias[cc];
        byv[nf] = bias[cc + 1];
    }
#pragma unroll
    for (int mf = 0; mf < 4; mf++) {
        const int r0 = row0 + wm + mf * 16 + gid;
        float rs0 = rowscale[r0], rs1 = rowscale[r0 + 8];
#pragma unroll
        for (int nf = 0; nf < 4; nf++) {
            const int cc = wn + nf * 8 + 2 * tig;
            __half2 v0 = __floats2half2_rn(fmaxf(c[mf][nf][0] + bxv[nf], 0.f) * rs0,
                                           fmaxf(c[mf][nf][1] + byv[nf], 0.f) * rs0);
            __half2 v1 = __floats2half2_rn(fmaxf(c[mf][nf][2] + bxv[nf], 0.f) * rs1,
                                           fmaxf(c[mf][nf][3] + byv[nf], 0.f) * rs1);
            *reinterpret_cast<__half2*>(&out[(size_t)r0 * 128 + cc]) = v0;
            *reinterpret_cast<__half2*>(&out[(size_t)(r0 + 8) * 128 + cc]) = v1;
        }
    }
}

// ---------------- fused layer-1 GEMM + global max pool ----------------
// Same MMA as gemm_h_kernel (K=128); epilogue computes relu(acc+bias) in fp32 and
// max-pools directly into pool[G,128] via smem-segment atomicMax (h1 never materialized).
// pool must be pre-zeroed; values >= 0 so uint-bit max == float max.
__global__ void __launch_bounds__(256, 2)
gemm_h_pool_kernel(const __half* __restrict__ A, const __half* __restrict__ Wt,
                   const float* __restrict__ bias, const int* __restrict__ batch,
                   float* __restrict__ pool, int K, int G)
{
    __shared__ __half As[2][128 * APAD];
    __shared__ __half Bs[2][128 * APAD];
    __shared__ unsigned int pool_s[4 * 128];   // up to 4 graph segments per 128-row block

    const int tid  = threadIdx.x;
    const int row0 = blockIdx.x * 128;
    const int lane = tid & 31;
    const int wid  = tid >> 5;
    const int gid  = lane >> 2;
    const int tig  = lane & 3;
    const int wm   = (wid & 1) * 64;
    const int wn   = (wid >> 1) * 32;

    for (int i = tid; i < 4 * 128; i += 256) pool_s[i] = 0u;

    float c[4][4][4];
#pragma unroll
    for (int i = 0; i < 4; i++)
#pragma unroll
        for (int j = 0; j < 4; j++)
#pragma unroll
            for (int r = 0; r < 4; r++) c[i][j][r] = 0.0f;

    const int KC = K >> 5;

    auto issue = [&](int kc, int buf) {
        const int k0 = kc << 5;
#pragma unroll
        for (int rpt = 0; rpt < 2; rpt++) {
            int i = tid + rpt * 256;
            int m = i >> 2, ch = i & 3;
            const __half* src = A + (size_t)(row0 + m) * K + k0 + ch * 8;
            uint32_t dst = (uint32_t)__cvta_generic_to_shared(&As[buf][m * APAD + ch * 8]);
            asm volatile("cp.async.cg.shared.global [%0], [%1], 16;" :: "r"(dst), "l"(src));
        }
#pragma unroll
        for (int rpt = 0; rpt < 2; rpt++) {
            int i = tid + rpt * 256;
            int n = i >> 2, ch = i & 3;
            const __half* src = Wt + (size_t)n * K + k0 + ch * 8;
            uint32_t dst = (uint32_t)__cvta_generic_to_shared(&Bs[buf][n * APAD + ch * 8]);
            asm volatile("cp.async.cg.shared.global [%0], [%1], 16;" :: "r"(dst), "l"(src));
        }
        asm volatile("cp.async.commit_group;" ::: "memory");
    };

    issue(0, 0);

    for (int kc = 0; kc < KC; kc++) {
        const int buf = kc & 1;
        asm volatile("cp.async.wait_group 0;" ::: "memory");
        __syncthreads();
        if (kc + 1 < KC) issue(kc + 1, buf ^ 1);

#pragma unroll
        for (int s = 0; s < 2; s++) {
            const int ks = s * 16;
            uint32_t a[4][4];
#pragma unroll
            for (int mf = 0; mf < 4; mf++) {
                const __half* ab = &As[buf][(wm + mf * 16 + gid) * APAD + ks];
                a[mf][0] = *reinterpret_cast<const uint32_t*>(&ab[2 * tig]);
                a[mf][1] = *reinterpret_cast<const uint32_t*>(&ab[8 * APAD + 2 * tig]);
                a[mf][2] = *reinterpret_cast<const uint32_t*>(&ab[2 * tig + 8]);
                a[mf][3] = *reinterpret_cast<const uint32_t*>(&ab[8 * APAD + 2 * tig + 8]);
            }
            uint32_t b[4][2];
#pragma unroll
            for (int nf = 0; nf < 4; nf++) {
                const __half* bb = &Bs[buf][(wn + nf * 8 + gid) * APAD + ks];
                b[nf][0] = *reinterpret_cast<const uint32_t*>(&bb[2 * tig]);
                b[nf][1] = *reinterpret_cast<const uint32_t*>(&bb[2 * tig + 8]);
            }
#pragma unroll
            for (int mf = 0; mf < 4; mf++)
#pragma unroll
                for (int nf = 0; nf < 4; nf++) {
                    asm volatile(
                        "mma.sync.aligned.m16n8k16.row.col.f32.f16.f16.f32 "
                        "{%0,%1,%2,%3}, {%4,%5,%6,%7}, {%8,%9}, {%0,%1,%2,%3};"
                        : "+f"(c[mf][nf][0]), "+f"(c[mf][nf][1]),
                          "+f"(c[mf][nf][2]), "+f"(c[mf][nf][3])
                        : "r"(a[mf][0]), "r"(a[mf][1]), "r"(a[mf][2]), "r"(a[mf][3]),
                          "r"(b[nf][0]), "r"(b[nf][1]));
                }
        }
        __syncthreads();
    }

    // epilogue: relu(acc+bias) -> per-segment smem max -> global atomicMax
    float bxv[4], byv[4];
#pragma unroll
    for (int nf = 0; nf < 4; nf++) {
        const int cc = wn + nf * 8 + 2 * tig;
        bxv[nf] = bias[cc];
        byv[nf] = bias[cc + 1];
    }
    const int gbase = __ldg(&batch[row0]);
#pragma unroll
    for (int mf = 0; mf < 4; mf++) {
        const int r0 = row0 + wm + mf * 16 + gid;
        const int seg0 = __ldg(&batch[r0]) - gbase;
        const int seg1 = __ldg(&batch[r0 + 8]) - gbase;
#pragma unroll
        for (int nf = 0; nf < 4; nf++) {
            const int cc = wn + nf * 8 + 2 * tig;
            float v00 = fmaxf(c[mf][nf][0] + bxv[nf], 0.f);
            float v01 = fmaxf(c[mf][nf][1] + byv[nf], 0.f);
            float v10 = fmaxf(c[mf][nf][2] + bxv[nf], 0.f);
            float v11 = fmaxf(c[mf][nf][3] + byv[nf], 0.f);
            atomicMax(&pool_s[seg0 * 128 + cc],     __float_as_uint(v00));
            atomicMax(&pool_s[seg0 * 128 + cc + 1], __float_as_uint(v01));
            atomicMax(&pool_s[seg1 * 128 + cc],     __float_as_uint(v10));
            atomicMax(&pool_s[seg1 * 128 + cc + 1], __float_as_uint(v11));
        }
    }
    __syncthreads();
    for (int i = tid; i < 4 * 128; i += 256) {
        int g = gbase + (i >> 7);
        unsigned int v = pool_s[i];
        if (g < G && v != 0u)
            atomicMax(reinterpret_cast<unsigned int*>(&pool[(size_t)g * 128 + (i & 127)]), v);
    }
}

// ---------------- FFMA GEMM for FF head (full fp32): out = relu(A@W + bias) ----------------
__global__ void __launch_bounds__(256, 2)
gemm_ff_kernel(const float* __restrict__ A, const float* __restrict__ W,
               const float* __restrict__ bias, float* __restrict__ out,
               int M, int K, int Nout)
{
    __shared__ float As[16 * 128];
    __shared__ float Bs[16 * 128];

    const int tid  = threadIdx.x;
    const int tx   = tid & 15;
    const int ty   = tid >> 4;
    const int row0 = blockIdx.x * 128;
    const int col0 = blockIdx.y * 128;

    float acc[8][8];
#pragma unroll
    for (int i = 0; i < 8; i++)
#pragma unroll
        for (int j = 0; j < 8; j++) acc[i][j] = 0.0f;

    const int KC = (K + 15) >> 4;
    for (int kc = 0; kc < KC; kc++) {
        const int k0 = kc << 4;
        for (int i = tid; i < 512; i += 256) {
            int m = i >> 2, kv = (i & 3) << 2;
            int row = row0 + m;
            float4 v = make_float4(0.f, 0.f, 0.f, 0.f);
            if (row < M && (k0 + kv) < K)
                v = *reinterpret_cast<const float4*>(&A[(size_t)row * K + k0 + kv]);
            As[(kv + 0) * 128 + m] = v.x;
            As[(kv + 1) * 128 + m] = v.y;
            As[(kv + 2) * 128 + m] = v.z;
            As[(kv + 3) * 128 + m] = v.w;
        }
        for (int i = tid; i < 512; i += 256) {
            int kk = i >> 5, n4 = (i & 31) << 2;
            float4 v = make_float4(0.f, 0.f, 0.f, 0.f);
            if ((k0 + kk) < K)
                v = *reinterpret_cast<const float4*>(&W[(size_t)(k0 + kk) * Nout + col0 + n4]);
            *reinterpret_cast<float4*>(&Bs[kk * 128 + n4]) = v;
        }
        __syncthreads();
#pragma unroll
        for (int kk = 0; kk < 16; kk++) {
            float4 a0 = *reinterpret_cast<const float4*>(&As[kk * 128 + ty * 8]);
            float4 a1 = *reinterpret_cast<const float4*>(&As[kk * 128 + ty * 8 + 4]);
            float4 b0 = *reinterpret_cast<const float4*>(&Bs[kk * 128 + tx * 8]);
            float4 b1 = *reinterpret_cast<const float4*>(&Bs[kk * 128 + tx * 8 + 4]);
            float av[8] = {a0.x, a0.y, a0.z, a0.w, a1.x, a1.y, a1.z, a1.w};
            float bv[8] = {b0.x, b0.y, b0.z, b0.w, b1.x, b1.y, b1.z, b1.w};
#pragma unroll
            for (int i = 0; i < 8; i++)
#pragma unroll
                for (int j = 0; j < 8; j++)
                    acc[i][j] += av[i] * bv[j];
        }
        __syncthreads();
    }

#pragma unroll
    for (int i = 0; i < 8; i++) {
        int row = row0 + ty * 8 + i;
        if (row >= M) break;
        const float4 b0 = *reinterpret_cast<const float4*>(&bias[col0 + tx * 8]);
        const float4 b1 = *reinterpret_cast<const float4*>(&bias[col0 + tx * 8 + 4]);
        float4 v0 = make_float4(fmaxf(acc[i][0] + b0.x, 0.f), fmaxf(acc[i][1] + b0.y, 0.f),
                                fmaxf(acc[i][2] + b0.z, 0.f), fmaxf(acc[i][3] + b0.w, 0.f));
        float4 v1 = make_float4(fmaxf(acc[i][4] + b1.x, 0.f), fmaxf(acc[i][5] + b1.y, 0.f),
                                fmaxf(acc[i][6] + b1.z, 0.f), fmaxf(acc[i][7] + b1.w, 0.f));
        float4* o = reinterpret_cast<float4*>(&out[(size_t)row * Nout + col0 + tx * 8]);
        o[0] = v0; o[1] = v1;
    }
}

// ---------------- launch ----------------
extern "C" void kernel_launch(void* const* d_in, const int* in_sizes, int n_in,
                              void* d_out, int out_size)
{
    const float* x     = (const float*)d_in[0];
    const int*   ei    = (const int*)d_in[1];
    const int*   batch = (const int*)d_in[2];
    const float* W0    = (const float*)d_in[3];
    const float* b0    = (const float*)d_in[4];
    const float* W1    = (const float*)d_in[5];
    const float* b1    = (const float*)d_in[6];
    const float* Wf0   = (const float*)d_in[7];
    const float* bf0   = (const float*)d_in[8];
    const float* Wf1   = (const float*)d_in[9];
    const float* bf1   = (const float*)d_in[10];
    float*       out   = (float*)d_out;

    const int F_IN = 78;
    const int N = in_sizes[0] / F_IN;
    const int E = in_sizes[1] / 2;
    const int G = out_size / HD;

    const int* src = ei;
    const int* dst = ei + E;

    int *p_counts, *p_rowptr, *p_cursor, *p_colidx, *p_bsum, *p_boff;
    float *p_dinv, *p_pool, *p_ff;
    __half *p_xs, *p_ax, *p_hh, *p_ah, *p_w0t, *p_w1t;
    cudaGetSymbolAddress((void**)&p_counts, g_counts);
    cudaGetSymbolAddress((void**)&p_rowptr, g_rowptr);
    cudaGetSymbolAddress((void**)&p_cursor, g_cursor);
    cudaGetSymbolAddress((void**)&p_colidx, g_colidx);
    cudaGetSymbolAddress((void**)&p_bsum,   g_bsum);
    cudaGetSymbolAddress((void**)&p_boff,   g_boff);
    cudaGetSymbolAddress((void**)&p_dinv,   g_dinv);
    cudaGetSymbolAddress((void**)&p_xs,     g_xs);
    cudaGetSymbolAddress((void**)&p_ax,     g_ax);
    cudaGetSymbolAddress((void**)&p_hh,     g_hh);
    cudaGetSymbolAddress((void**)&p_ah,     g_ah);
    cudaGetSymbolAddress((void**)&p_w0t,    g_w0t);
    cudaGetSymbolAddress((void**)&p_w1t,    g_w1t);
    cudaGetSymbolAddress((void**)&p_pool,   g_pool);
    cudaGetSymbolAddress((void**)&p_ff,     g_ff);

    const int TB = 256;
    int gE = (E + TB - 1) / TB;
    int NB = (N + CHUNK - 1) / CHUNK;
    int gW = (N * 32 + TB - 1) / TB;   // warp-per-node grids

    // ---- CSR build + norm ----
    cudaMemsetAsync(p_counts, 0, (size_t)N * sizeof(int));
    count_deg_kernel<<<gE, TB>>>(dst, p_counts, E);
    scan_chunk_sum<<<NB, 256>>>(p_counts, p_bsum, p_dinv, N);
    scan_bsum<<<1, 512>>>(p_bsum, p_boff, NB);
    scan_final<<<NB, CHUNK>>>(p_counts, p_boff, p_rowptr, p_cursor, N);
    fill_csr_kernel<<<gE, TB>>>(src, dst, p_cursor, p_colidx, E);

    // ---- conversions (xs = x * dinv), pool zero-init ----
    conv_x_kernel<<<(N * 40 + TB - 1) / TB, TB>>>(x, p_dinv, (__half2*)p_xs, N);
    conv_w_kernel<<<(128 * 96 + 128 * 128 + TB - 1) / TB, TB>>>(W0, W1, p_w0t, p_w1t);
    cudaMemsetAsync(p_pool, 0, (size_t)G * HD * sizeof(float));

    // ---- layer 0: aggregate-then-transform; GEMM stores h0*dinv ----
    agg0_kernel<<<gW, TB>>>((const uint2*)p_xs, p_rowptr, p_colidx, p_dinv, (uint2*)p_ax, N);
    gemm_h_kernel<<<N / 128, TB>>>(p_ax, p_w0t, b0, p_dinv, p_hh, 96);

    // ---- layer 1: agg + fused GEMM/max-pool (h1 never materialized) ----
    agg1_kernel<<<gW, TB>>>((const uint2*)p_hh, p_rowptr, p_colidx, p_dinv, (uint2*)p_ah, N);
    gemm_h_pool_kernel<<<N / 128, TB>>>(p_ah, p_w1t, b1, batch, p_pool, 128, G);

    // ---- FF head (fp32) ----
    {
        dim3 grid((G + 127) / 128, 2);
        gemm_ff_kernel<<<grid, TB>>>(p_pool, Wf0, bf0, p_ff, G, HD, 256);
    }
    {
        dim3 grid((G + 127) / 128, 1);
        gemm_ff_kernel<<<grid, TB>>>(p_ff, Wf1, bf1, out, G, 256, HD);
    }
}